// round 8
// baseline (speedup 1.0000x reference)
#include <cuda_runtime.h>
#include <cstddef>

#define G_CELLS 8000
#define T_STEPS 730
#define CH 10              // steps per chunk; 730 = 10 * 73
#define NCHUNK 73
#define CPB 64             // cells per block; 8000 = 125 * 64
#define NEARZERO_F 1e-5f

__device__ __forceinline__ float ex2f_(float x) {
    float r; asm("ex2.approx.f32 %0, %1;" : "=f"(r) : "f"(x)); return r;
}
__device__ __forceinline__ float lg2f_(float x) {
    float r; asm("lg2.approx.f32 %0, %1;" : "=f"(r) : "f"(x)); return r;
}

// Named barriers: full0=1, full1=2 (producer->consumer),
//                 free0=3, free1=4 (consumer->producer). count = 96 threads.
#define BAR_SYNC(id)   asm volatile("bar.sync %0, 96;"   :: "r"(id) : "memory")
#define BAR_ARRIVE(id) asm volatile("bar.arrive %0, 96;" :: "r"(id) : "memory")

__global__ __launch_bounds__(96, 1) void hbv_kernel(
    const float* __restrict__ xphy,    // [730, 8000, 3] (P, T, PET)
    const float* __restrict__ params,  // [730, 8000, 14]
    float* __restrict__ out)           // [730, 8000]
{
    __shared__ float2 buf[2][CH][CPB];   // (inflow, PET) double-buffered ring

    const int tid = threadIdx.x;
    const bool is_producer = (tid >= 32);

    // BETA, FC, K0, K1, K2, LP, PERCmax, UZL, TT, CFMAX, CFR, CWH, BETAET, C
    const float lo[14] = {1.0f, 50.0f, 0.05f, 0.01f, 0.001f, 0.2f, 0.0f,
                          0.0f, -2.5f, 0.5f, 0.0f, 0.0f, 0.3f, 0.0f};
    const float hi[14] = {6.0f, 1000.0f, 0.9f, 0.5f, 0.2f, 1.0f, 10.0f,
                          100.0f, 2.5f, 10.0f, 0.1f, 0.2f, 5.0f, 1.0f};

    auto load_phy = [&](int g, float* phy) {
        const float* pr =
            params + ((size_t)(T_STEPS - 1) * G_CELLS + (size_t)g) * 14;
#pragma unroll
        for (int i = 0; i < 14; i++) {
            const float s = 1.0f / (1.0f + __expf(-pr[i]));
            phy[i] = fmaf(s, hi[i] - lo[i], lo[i]);
        }
    };

    if (is_producer) {
        // ------------- PRODUCER (64 threads, 1 cell each): snow + loads -------------
        const int lane = tid - 32;                  // 0..63
        const int g = blockIdx.x * CPB + lane;
        float phy[14];
        load_phy(g, phy);
        const float TT = phy[8], CFMAX = phy[9], CWH = phy[11];
        const float CFRCF = phy[10] * phy[9];

        float SP = 0.001f, MW = 0.001f;

        auto snow_adv = [&](float P, float Tm) -> float {
            const bool  rain = (Tm >= TT);
            const float RAIN = rain ? P : 0.0f;
            const float SNOW = rain ? 0.0f : P;
            const float w    = (rain ? CFMAX : CFRCF) * (Tm - TT);
            const float SP1  = SP + SNOW;
            const float transfer = fminf(fmaxf(w, -MW), SP1);
            SP = SP1 - transfer;
            const float MW2 = MW + transfer;
            const float v   = fmaf(-CWH, SP, MW2);
            const float tosoil = fmaxf(v, 0.0f);
            MW = MW2 - tosoil;
            return RAIN + tosoil;
        };

        // Raw-input ring: next chunk's inputs, loaded one chunk early.
        float rP[CH], rT[CH], rE[CH];
        const float* xp = xphy + (size_t)g * 3;     // step 0
#pragma unroll
        for (int i = 0; i < CH; i++) {
            rP[i] = xp[0]; rT[i] = xp[1]; rE[i] = xp[2];
            xp += (size_t)G_CELLS * 3;
        }
        for (int k = 0; k < NCHUNK - 1; ++k) {
            if (k >= 2) BAR_SYNC(3 + (k & 1));      // wait: slot free
            const int s = k & 1;
#pragma unroll
            for (int i = 0; i < CH; i++) {
                const float P = rP[i], Tm = rT[i], PE = rE[i];
                rP[i] = xp[0]; rT[i] = xp[1]; rE[i] = xp[2];
                xp += (size_t)G_CELLS * 3;
                const float inflow = snow_adv(P, Tm);
                buf[s][i][lane] = make_float2(inflow, PE);
            }
            asm volatile("membar.cta;" ::: "memory");
            BAR_ARRIVE(1 + (k & 1));                // signal: slot full
        }
        {   // final chunk: no loads
            const int k = NCHUNK - 1;
            BAR_SYNC(3 + (k & 1));
            const int s = k & 1;
#pragma unroll
            for (int i = 0; i < CH; i++) {
                const float inflow = snow_adv(rP[i], rT[i]);
                buf[s][i][lane] = make_float2(inflow, rE[i]);
            }
            asm volatile("membar.cta;" ::: "memory");
            BAR_ARRIVE(1 + (k & 1));
        }
    } else {
        // ------------- CONSUMER (32 threads, 2 cells each): hydro chain -------------
        const int lane = tid;                       // 0..31
        float BETA[2], FC[2], K2[2], PERCmax[2], BETAET[2], C[2];
        float invFC[2], clgA[2], clgB[2], sFCc[2], oneK0[2], K0UZL[2], oneK1[2];
        float SM[2], SUZ[2], SLZ[2], CSLZ[2], omcf[2];
        float* op[2];

#pragma unroll
        for (int c = 0; c < 2; ++c) {
            const int g = blockIdx.x * CPB + lane + c * 32;
            float phy[14];
            load_phy(g, phy);
            BETA[c] = phy[0]; FC[c] = phy[1];
            const float K0 = phy[2], K1 = phy[3];
            K2[c] = phy[4];
            const float LP = phy[5];
            PERCmax[c] = phy[6];
            const float UZL = phy[7];
            BETAET[c] = phy[12]; C[c] = phy[13];

            invFC[c] = 1.0f / FC[c];
            clgA[c]  = BETA[c]   * lg2f_(invFC[c]);
            clgB[c]  = BETAET[c] * lg2f_(1.0f / (LP * FC[c]));
            sFCc[c]  = BETAET[c] * lg2f_(1.0f / LP);
            oneK0[c] = 1.0f - K0;
            K0UZL[c] = K0 * UZL;
            oneK1[c] = 1.0f - K1;

            SM[c] = SUZ[c] = SLZ[c] = 0.001f;
            CSLZ[c] = C[c] * 0.001f;
            omcf[c] = 1.0f - CSLZ[c] * invFC[c];
            op[c] = out + g;
        }

        for (int k = 0; k < NCHUNK; ++k) {
            BAR_SYNC(1 + (k & 1));                  // wait: slot full
            const int s = k & 1;
            float2 v[2][CH];
#pragma unroll
            for (int i = 0; i < CH; i++) {
                v[0][i] = buf[s][i][lane];
                v[1][i] = buf[s][i][lane + 32];
            }

#pragma unroll
            for (int i = 0; i < CH; i++) {
                // Two independent chains, interleaved by the unrolled c-loop
                // (ptxas weaves them; each fills the other's stall holes).
#pragma unroll
                for (int c = 0; c < 2; ++c) {
                    const float inflow = v[c][i].x, PETt = v[c][i].y;

                    const float t1 = SM[c] + inflow;
                    const float s1 =
                        fminf(fmaf(BETA[c], lg2f_(SM[c]), clgA[c]), 0.0f);
                    const float e1 = ex2f_(s1);          // min((SM/FC)^B, 1)
                    const float SM1 = fmaf(-inflow, e1, t1);
                    const float SM2 = fminf(SM1, FC[c]);
                    const float s2 =
                        fminf(fmaf(BETAET[c], lg2f_(SM1), clgB[c]), sFCc[c]);
                    const float e2 = ex2f_(s2);
                    const float floor3 = fmaxf(SM2 - PETt, NEARZERO_F);
                    const float SM3 = fmaxf(fmaf(-PETt, e2, SM2), floor3);
                    const float a = fmaf(omcf[c], SM3, CSLZ[c]);
                    const float SMn = fmaxf(fminf(a, SM3 + SLZ[c]), SM3);
                    const float cap = SMn - SM3;
                    SM[c] = SMn;

                    const float SUZ1 = SUZ[c] + (t1 - SM2);
                    const float PERC = fminf(SUZ1, PERCmax[c]);
                    const float SUZ2 = fmaxf(SUZ1 - PERCmax[c], 0.0f);
                    const float SUZ3 =
                        fminf(SUZ2, fmaf(oneK0[c], SUZ2, K0UZL[c]));
                    SUZ[c] = oneK1[c] * SUZ3;
                    const float Q01 = SUZ2 - SUZ[c];

                    const float SLZ1 = fmaxf(SLZ[c] - cap, NEARZERO_F) + PERC;
                    const float Q2 = K2[c] * SLZ1;
                    SLZ[c] = SLZ1 - Q2;
                    CSLZ[c] = C[c] * SLZ[c];
                    omcf[c] = fmaf(-CSLZ[c], invFC[c], 1.0f);

                    *op[c] = Q01 + Q2;
                    op[c] += G_CELLS;
                }
            }
            BAR_ARRIVE(3 + (k & 1));                // signal: slot free
        }
    }
}

extern "C" void kernel_launch(void* const* d_in, const int* in_sizes, int n_in,
                              void* d_out, int out_size) {
    const float* xphy   = (const float*)d_in[0];   // 730*8000*3
    const float* params = (const float*)d_in[1];   // 730*8000*14
    float* out = (float*)d_out;                    // 730*8000

    hbv_kernel<<<125, 96>>>(xphy, params, out);    // 125 * 64 cells = 8000
}

// round 9
// speedup vs baseline: 1.1322x; 1.1322x over previous
#include <cuda_runtime.h>
#include <cstddef>

#define G_CELLS 8000
#define T_STEPS 730
#define CH 10              // steps per chunk; 730 = 10 * 73
#define NCHUNK 73
#define CPB 64             // cells per block; 8000 = 125 * 64
#define NEARZERO_F 1e-5f

__device__ __forceinline__ float ex2f_(float x) {
    float r; asm("ex2.approx.f32 %0, %1;" : "=f"(r) : "f"(x)); return r;
}
__device__ __forceinline__ float lg2f_(float x) {
    float r; asm("lg2.approx.f32 %0, %1;" : "=f"(r) : "f"(x)); return r;
}

// Named barriers: full0=1, full1=2 (producer->consumer),
//                 free0=3, free1=4 (consumer->producer). count = 128.
#define BAR_SYNC(id)   asm volatile("bar.sync %0, 128;"   :: "r"(id) : "memory")
#define BAR_ARRIVE(id) asm volatile("bar.arrive %0, 128;" :: "r"(id) : "memory")
#define MEMBAR_CTA()   asm volatile("membar.cta;" ::: "memory")

__global__ __launch_bounds__(128, 1) void hbv_kernel(
    const float* __restrict__ xphy,    // [730, 8000, 3] (P, T, PET)
    const float* __restrict__ params,  // [730, 8000, 14]
    float* __restrict__ out)           // [730, 8000]
{
    __shared__ float2 buf[2][CH][CPB];   // (inflow, PET) producer -> consumer
    __shared__ float  qbuf[2][CH][CPB];  // Q results    consumer -> producer

    const int tid  = threadIdx.x;
    const int lane = tid & 63;                 // cell slot within block
    const bool is_producer = (tid >= 64);
    const int g = blockIdx.x * CPB + lane;     // always < 8000

    // BETA, FC, K0, K1, K2, LP, PERCmax, UZL, TT, CFMAX, CFR, CWH, BETAET, C
    const float lo[14] = {1.0f, 50.0f, 0.05f, 0.01f, 0.001f, 0.2f, 0.0f,
                          0.0f, -2.5f, 0.5f, 0.0f, 0.0f, 0.3f, 0.0f};
    const float hi[14] = {6.0f, 1000.0f, 0.9f, 0.5f, 0.2f, 1.0f, 10.0f,
                          100.0f, 2.5f, 10.0f, 0.1f, 0.2f, 5.0f, 1.0f};

    const float* pr = params + ((size_t)(T_STEPS - 1) * G_CELLS + (size_t)g) * 14;
    float phy[14];
#pragma unroll
    for (int i = 0; i < 14; i++) {
        const float s = 1.0f / (1.0f + __expf(-pr[i]));
        phy[i] = fmaf(s, hi[i] - lo[i], lo[i]);
    }

    if (is_producer) {
        // -------- PRODUCER: snow recurrence + input loads + Q store-out --------
        const float TT = phy[8], CFMAX = phy[9], CWH = phy[11];
        const float CFRCF = phy[10] * phy[9];

        float SP = 0.001f, MW = 0.001f;

        auto snow_adv = [&](float P, float Tm) -> float {
            const bool  rain = (Tm >= TT);
            const float RAIN = rain ? P : 0.0f;
            const float SNOW = rain ? 0.0f : P;
            const float w    = (rain ? CFMAX : CFRCF) * (Tm - TT);
            const float SP1  = SP + SNOW;
            const float transfer = fminf(fmaxf(w, -MW), SP1);
            SP = SP1 - transfer;
            const float MW2 = MW + transfer;
            const float v   = fmaf(-CWH, SP, MW2);
            const float tosoil = fmaxf(v, 0.0f);
            MW = MW2 - tosoil;
            return RAIN + tosoil;
        };

        // Flush chunk m's Q values (already in qbuf slot m&1) to GMEM.
        auto flush_q = [&](int m) {
            float* o = out + (size_t)(m * CH) * G_CELLS + g;
            const int s = m & 1;
#pragma unroll
            for (int i = 0; i < CH; i++) {
                o[(size_t)i * G_CELLS] = qbuf[s][i][lane];
            }
        };

        // Raw-input ring: next chunk's inputs, loaded one chunk early.
        float rP[CH], rT[CH], rE[CH];
        const float* xp = xphy + (size_t)g * 3;     // step 0
#pragma unroll
        for (int i = 0; i < CH; i++) {
            rP[i] = xp[0]; rT[i] = xp[1]; rE[i] = xp[2];
            xp += (size_t)G_CELLS * 3;
        }
        for (int k = 0; k < NCHUNK - 1; ++k) {
            if (k >= 2) {
                BAR_SYNC(3 + (k & 1));      // consumer done chunk k-2
                flush_q(k - 2);             // its Q block is ready in qbuf
            }
            const int s = k & 1;
#pragma unroll
            for (int i = 0; i < CH; i++) {
                const float P = rP[i], Tm = rT[i], PE = rE[i];
                rP[i] = xp[0]; rT[i] = xp[1]; rE[i] = xp[2];
                xp += (size_t)G_CELLS * 3;
                const float inflow = snow_adv(P, Tm);
                buf[s][i][lane] = make_float2(inflow, PE);
            }
            MEMBAR_CTA();
            BAR_ARRIVE(1 + (k & 1));        // slot full
        }
        {   // final chunk: no loads
            const int k = NCHUNK - 1;
            BAR_SYNC(3 + (k & 1));
            flush_q(k - 2);
            const int s = k & 1;
#pragma unroll
            for (int i = 0; i < CH; i++) {
                const float inflow = snow_adv(rP[i], rT[i]);
                buf[s][i][lane] = make_float2(inflow, rE[i]);
            }
            MEMBAR_CTA();
            BAR_ARRIVE(1 + (k & 1));
        }
        // Tail: flush the last two chunks as consumer finishes them.
        BAR_SYNC(3 + ((NCHUNK - 2) & 1));
        flush_q(NCHUNK - 2);
        BAR_SYNC(3 + ((NCHUNK - 1) & 1));
        flush_q(NCHUNK - 1);
    } else {
        // -------- CONSUMER: SM/SUZ/SLZ chain, Q to smem --------
        const float BETA = phy[0], FC = phy[1], K0 = phy[2], K1 = phy[3];
        const float K2 = phy[4], LP = phy[5], PERCmax = phy[6], UZL = phy[7];
        const float BETAET = phy[12], C = phy[13];

        const float invFC = 1.0f / FC;
        const float clgA  = BETA   * lg2f_(invFC);
        const float clgB  = BETAET * lg2f_(1.0f / (LP * FC));
        const float oneK0 = 1.0f - K0;
        const float K0UZL = K0 * UZL;
        const float oneK1 = 1.0f - K1;

        float SM = 0.001f, SUZ = 0.001f, SLZ = 0.001f;
        float CSLZ = C * SLZ;
        float omcf = 1.0f - CSLZ * invFC;

        for (int k = 0; k < NCHUNK; ++k) {
            BAR_SYNC(1 + (k & 1));                  // wait: slot full
            const int s = k & 1;
            float2 v[CH];
#pragma unroll
            for (int i = 0; i < CH; i++) v[i] = buf[s][i][lane];

#pragma unroll
            for (int i = 0; i < CH; i++) {
                const float inflow = v[i].x, PETt = v[i].y;

                const float t1 = SM + inflow;
                // e1 = min((SM/FC)^BETA, 1), clamp in log domain
                const float s1 = fminf(fmaf(BETA, lg2f_(SM), clgA), 0.0f);
                const float e1 = ex2f_(s1);
                const float SM1 = fmaf(-inflow, e1, t1);   // >= SM
                const float SM2 = fminf(SM1, FC);          // parallel to lg2
                // s2 clamp at 0 subsumes both SM1<=FC and ef<=1 clamps
                const float s2 = fminf(fmaf(BETAET, lg2f_(SM1), clgB), 0.0f);
                const float e2 = ex2f_(s2);                // <= 1
                const float SM3 = fmaxf(fmaf(-PETt, e2, SM2), NEARZERO_F);
                // capillary: cap = CSLZ*(1-SM3/FC); clamps proven redundant
                // (C<1 => CSLZ<SLZ; SM3<=FC => factor in [0,1])
                const float SMn = fmaf(omcf, SM3, CSLZ);
                const float cap = SMn - SM3;               // off-path
                SM = SMn;

                const float SUZ1 = SUZ + (t1 - SM2);       // + recharge+excess
                const float PERC = fminf(SUZ1, PERCmax);
                const float SUZ2 = fmaxf(SUZ1 - PERCmax, 0.0f);
                const float SUZ3 = fminf(SUZ2, fmaf(oneK0, SUZ2, K0UZL));
                SUZ = oneK1 * SUZ3;
                const float Q01 = SUZ2 - SUZ;

                const float SLZ1 = fmaxf(SLZ - cap, NEARZERO_F) + PERC;
                const float Q2 = K2 * SLZ1;
                SLZ = SLZ1 - Q2;
                CSLZ = C * SLZ;
                omcf = fmaf(-CSLZ, invFC, 1.0f);

                qbuf[s][i][lane] = Q01 + Q2;   // STS instead of STG
            }
            MEMBAR_CTA();                       // order Q STS before arrive
            BAR_ARRIVE(3 + (k & 1));            // slot free + Q ready
        }
    }
}

extern "C" void kernel_launch(void* const* d_in, const int* in_sizes, int n_in,
                              void* d_out, int out_size) {
    const float* xphy   = (const float*)d_in[0];   // 730*8000*3
    const float* params = (const float*)d_in[1];   // 730*8000*14
    float* out = (float*)d_out;                    // 730*8000

    hbv_kernel<<<125, 128>>>(xphy, params, out);   // 125 * 64 cells = 8000
}

// round 10
// speedup vs baseline: 1.1390x; 1.0060x over previous
#include <cuda_runtime.h>
#include <cstddef>

#define G_CELLS 8000
#define T_STEPS 730
#define CH 10              // steps per chunk; 730 = 10 * 73
#define NCHUNK 73
#define CPB 64             // cells per block; 8000 = 125 * 64
#define NEARZERO_F 1e-5f

__device__ __forceinline__ float ex2f_(float x) {
    float r; asm("ex2.approx.f32 %0, %1;" : "=f"(r) : "f"(x)); return r;
}
__device__ __forceinline__ float lg2f_(float x) {
    float r; asm("lg2.approx.f32 %0, %1;" : "=f"(r) : "f"(x)); return r;
}

// Named barriers: full0=1, full1=2 (producer->consumer),
//                 free0=3, free1=4 (consumer->producer). count = 128.
// PTX: bar.sync / bar.arrive perform a memory fence equivalent to membar.cta,
// so no explicit membar is needed around the smem handoffs.
#define BAR_SYNC(id)   asm volatile("bar.sync %0, 128;"   :: "r"(id) : "memory")
#define BAR_ARRIVE(id) asm volatile("bar.arrive %0, 128;" :: "r"(id) : "memory")

__global__ __launch_bounds__(128, 1) void hbv_kernel(
    const float* __restrict__ xphy,    // [730, 8000, 3] (P, T, PET)
    const float* __restrict__ params,  // [730, 8000, 14]
    float* __restrict__ out)           // [730, 8000]
{
    __shared__ float2 buf[2][CH][CPB];   // (inflow, PET) producer -> consumer
    __shared__ float  qbuf[2][CH][CPB];  // Q results    consumer -> producer

    const int tid  = threadIdx.x;
    const int lane = tid & 63;                 // cell slot within block
    const bool is_producer = (tid >= 64);
    const int g = blockIdx.x * CPB + lane;     // always < 8000

    // BETA, FC, K0, K1, K2, LP, PERCmax, UZL, TT, CFMAX, CFR, CWH, BETAET, C
    const float lo[14] = {1.0f, 50.0f, 0.05f, 0.01f, 0.001f, 0.2f, 0.0f,
                          0.0f, -2.5f, 0.5f, 0.0f, 0.0f, 0.3f, 0.0f};
    const float hi[14] = {6.0f, 1000.0f, 0.9f, 0.5f, 0.2f, 1.0f, 10.0f,
                          100.0f, 2.5f, 10.0f, 0.1f, 0.2f, 5.0f, 1.0f};

    const float* pr = params + ((size_t)(T_STEPS - 1) * G_CELLS + (size_t)g) * 14;
    float phy[14];
#pragma unroll
    for (int i = 0; i < 14; i++) {
        const float s = 1.0f / (1.0f + __expf(-pr[i]));
        phy[i] = fmaf(s, hi[i] - lo[i], lo[i]);
    }

    if (is_producer) {
        // -------- PRODUCER: snow recurrence + input loads + Q store-out --------
        const float TT = phy[8], CFMAX = phy[9], CWH = phy[11];
        const float CFRCF = phy[10] * phy[9];

        float SP = 0.001f, MW = 0.001f;

        auto snow_adv = [&](float P, float Tm) -> float {
            const bool  rain = (Tm >= TT);
            const float RAIN = rain ? P : 0.0f;
            const float SNOW = rain ? 0.0f : P;
            const float w    = (rain ? CFMAX : CFRCF) * (Tm - TT);
            const float SP1  = SP + SNOW;
            const float transfer = fminf(fmaxf(w, -MW), SP1);
            SP = SP1 - transfer;
            const float MW2 = MW + transfer;
            const float v   = fmaf(-CWH, SP, MW2);
            const float tosoil = fmaxf(v, 0.0f);
            MW = MW2 - tosoil;
            return RAIN + tosoil;
        };

        // Flush chunk m's Q values (already in qbuf slot m&1) to GMEM.
        auto flush_q = [&](int m) {
            float* o = out + (size_t)(m * CH) * G_CELLS + g;
            const int s = m & 1;
#pragma unroll
            for (int i = 0; i < CH; i++) {
                o[(size_t)i * G_CELLS] = qbuf[s][i][lane];
            }
        };

        // Raw-input ring: next chunk's inputs, loaded one chunk early.
        float rP[CH], rT[CH], rE[CH];
        const float* xp = xphy + (size_t)g * 3;     // step 0
#pragma unroll
        for (int i = 0; i < CH; i++) {
            rP[i] = xp[0]; rT[i] = xp[1]; rE[i] = xp[2];
            xp += (size_t)G_CELLS * 3;
        }
        for (int k = 0; k < NCHUNK - 1; ++k) {
            if (k >= 2) {
                BAR_SYNC(3 + (k & 1));      // consumer done chunk k-2
                flush_q(k - 2);             // its Q block is ready in qbuf
            }
            const int s = k & 1;
#pragma unroll
            for (int i = 0; i < CH; i++) {
                const float P = rP[i], Tm = rT[i], PE = rE[i];
                rP[i] = xp[0]; rT[i] = xp[1]; rE[i] = xp[2];
                xp += (size_t)G_CELLS * 3;
                const float inflow = snow_adv(P, Tm);
                buf[s][i][lane] = make_float2(inflow, PE);
            }
            BAR_ARRIVE(1 + (k & 1));        // slot full (arrive = release fence)
        }
        {   // final chunk: no loads
            const int k = NCHUNK - 1;
            BAR_SYNC(3 + (k & 1));
            flush_q(k - 2);
            const int s = k & 1;
#pragma unroll
            for (int i = 0; i < CH; i++) {
                const float inflow = snow_adv(rP[i], rT[i]);
                buf[s][i][lane] = make_float2(inflow, rE[i]);
            }
            BAR_ARRIVE(1 + (k & 1));
        }
        // Tail: flush the last two chunks as consumer finishes them.
        BAR_SYNC(3 + ((NCHUNK - 2) & 1));
        flush_q(NCHUNK - 2);
        BAR_SYNC(3 + ((NCHUNK - 1) & 1));
        flush_q(NCHUNK - 1);
    } else {
        // -------- CONSUMER: SM/SUZ/SLZ chain, Q to smem --------
        const float BETA = phy[0], FC = phy[1], K0 = phy[2], K1 = phy[3];
        const float K2 = phy[4], LP = phy[5], PERCmax = phy[6], UZL = phy[7];
        const float BETAET = phy[12], C = phy[13];

        const float invFC = 1.0f / FC;
        const float clgA  = BETA   * lg2f_(invFC);
        const float clgB  = BETAET * lg2f_(1.0f / (LP * FC));
        const float oneK0 = 1.0f - K0;
        const float K0UZL = K0 * UZL;
        const float oneK1 = 1.0f - K1;

        float SM = 0.001f, SUZ = 0.001f, SLZ = 0.001f;
        float CSLZ = C * SLZ;
        float omcf = 1.0f - CSLZ * invFC;

        for (int k = 0; k < NCHUNK; ++k) {
            BAR_SYNC(1 + (k & 1));                  // wait: slot full (acquire)
            const int s = k & 1;
            float2 v[CH];
#pragma unroll
            for (int i = 0; i < CH; i++) v[i] = buf[s][i][lane];

#pragma unroll
            for (int i = 0; i < CH; i++) {
                const float inflow = v[i].x, PETt = v[i].y;

                const float t1 = SM + inflow;
                // e1 = min((SM/FC)^BETA, 1), clamp in log domain
                const float s1 = fminf(fmaf(BETA, lg2f_(SM), clgA), 0.0f);
                const float e1 = ex2f_(s1);
                const float SM1 = fmaf(-inflow, e1, t1);   // >= SM
                const float SM2 = fminf(SM1, FC);          // parallel to lg2
                // s2 clamp at 0 subsumes both SM1<=FC and ef<=1 clamps
                const float s2 = fminf(fmaf(BETAET, lg2f_(SM1), clgB), 0.0f);
                const float e2 = ex2f_(s2);                // <= 1

                // ---- off-path response front half (fills e2 MUFU latency) ----
                const float SUZ1 = SUZ + (t1 - SM2);       // + recharge+excess
                const float PERC = fminf(SUZ1, PERCmax);
                const float SUZ2 = fmaxf(SUZ1 - PERCmax, 0.0f);
                const float SUZ3 = fminf(SUZ2, fmaf(oneK0, SUZ2, K0UZL));
                SUZ = oneK1 * SUZ3;
                const float Q01 = SUZ2 - SUZ;

                // ---- chain tail ----
                const float SM3 = fmaxf(fmaf(-PETt, e2, SM2), NEARZERO_F);
                // capillary: cap = CSLZ*(1-SM3/FC); clamps proven redundant
                // (C<1 => CSLZ<SLZ; SM3<=FC => factor in [0,1])
                const float SMn = fmaf(omcf, SM3, CSLZ);
                const float cap = SMn - SM3;               // off-path
                SM = SMn;

                // ---- off-path response back half ----
                const float SLZ1 = fmaxf(SLZ - cap, NEARZERO_F) + PERC;
                const float Q2 = K2 * SLZ1;
                SLZ = SLZ1 - Q2;
                CSLZ = C * SLZ;
                omcf = fmaf(-CSLZ, invFC, 1.0f);

                qbuf[s][i][lane] = Q01 + Q2;   // STS instead of STG
            }
            BAR_ARRIVE(3 + (k & 1));            // slot free + Q ready (release)
        }
    }
}

extern "C" void kernel_launch(void* const* d_in, const int* in_sizes, int n_in,
                              void* d_out, int out_size) {
    const float* xphy   = (const float*)d_in[0];   // 730*8000*3
    const float* params = (const float*)d_in[1];   // 730*8000*14
    float* out = (float*)d_out;                    // 730*8000

    hbv_kernel<<<125, 128>>>(xphy, params, out);   // 125 * 64 cells = 8000
}

// round 11
// speedup vs baseline: 1.1454x; 1.0056x over previous
#include <cuda_runtime.h>
#include <cstddef>

#define G_CELLS 8000
#define T_STEPS 730
#define CH 10              // steps per chunk; 730 = 10 * 73
#define NCHUNK 73
#define CPB 64             // cells per block; 8000 = 125 * 64
#define NEARZERO_F 1e-5f

__device__ __forceinline__ float ex2f_(float x) {
    float r; asm("ex2.approx.f32 %0, %1;" : "=f"(r) : "f"(x)); return r;
}
__device__ __forceinline__ float lg2f_(float x) {
    float r; asm("lg2.approx.f32 %0, %1;" : "=f"(r) : "f"(x)); return r;
}

// Named barriers at SUPER-CHUNK (2-chunk) granularity, 4-slot data ring.
// full: id 1+(j&1) (producer -> consumer), free: id 3+(j&1) (consumer -> producer),
// j = super-chunk index = k>>1. count = 128 threads. bar.sync/arrive carry
// membar.cta-equivalent fence semantics.
#define BAR_SYNC(id)   asm volatile("bar.sync %0, 128;"   :: "r"(id) : "memory")
#define BAR_ARRIVE(id) asm volatile("bar.arrive %0, 128;" :: "r"(id) : "memory")

__global__ __launch_bounds__(128, 1) void hbv_kernel(
    const float* __restrict__ xphy,    // [730, 8000, 3] (P, T, PET)
    const float* __restrict__ params,  // [730, 8000, 14]
    float* __restrict__ out)           // [730, 8000]
{
    __shared__ float2 buf[4][CH][CPB];   // (inflow, PET) producer -> consumer
    __shared__ float  qbuf[4][CH][CPB];  // Q results    consumer -> producer

    const int tid  = threadIdx.x;
    const int lane = tid & 63;                 // cell slot within block
    const bool is_producer = (tid >= 64);
    const int g = blockIdx.x * CPB + lane;     // always < 8000

    // BETA, FC, K0, K1, K2, LP, PERCmax, UZL, TT, CFMAX, CFR, CWH, BETAET, C
    const float lo[14] = {1.0f, 50.0f, 0.05f, 0.01f, 0.001f, 0.2f, 0.0f,
                          0.0f, -2.5f, 0.5f, 0.0f, 0.0f, 0.3f, 0.0f};
    const float hi[14] = {6.0f, 1000.0f, 0.9f, 0.5f, 0.2f, 1.0f, 10.0f,
                          100.0f, 2.5f, 10.0f, 0.1f, 0.2f, 5.0f, 1.0f};

    const float* pr = params + ((size_t)(T_STEPS - 1) * G_CELLS + (size_t)g) * 14;
    float phy[14];
#pragma unroll
    for (int i = 0; i < 14; i++) {
        const float s = 1.0f / (1.0f + __expf(-pr[i]));
        phy[i] = fmaf(s, hi[i] - lo[i], lo[i]);
    }

    if (is_producer) {
        // -------- PRODUCER: snow recurrence + input loads + Q store-out --------
        const float TT = phy[8], CFMAX = phy[9], CWH = phy[11];
        const float CFRCF = phy[10] * phy[9];

        float SP = 0.001f, MW = 0.001f;

        auto snow_adv = [&](float P, float Tm) -> float {
            const bool  rain = (Tm >= TT);
            const float RAIN = rain ? P : 0.0f;
            const float SNOW = rain ? 0.0f : P;
            const float w    = (rain ? CFMAX : CFRCF) * (Tm - TT);
            const float SP1  = SP + SNOW;
            const float transfer = fminf(fmaxf(w, -MW), SP1);
            SP = SP1 - transfer;
            const float MW2 = MW + transfer;
            const float v   = fmaf(-CWH, SP, MW2);
            const float tosoil = fmaxf(v, 0.0f);
            MW = MW2 - tosoil;
            return RAIN + tosoil;
        };

        // Flush chunk m's Q values (in qbuf slot m&3) to GMEM.
        auto flush_q = [&](int m) {
            float* o = out + (size_t)(m * CH) * G_CELLS + g;
            const int s = m & 3;
#pragma unroll
            for (int i = 0; i < CH; i++) {
                o[(size_t)i * G_CELLS] = qbuf[s][i][lane];
            }
        };

        // Raw-input ring: next chunk's inputs, loaded one chunk early.
        float rP[CH], rT[CH], rE[CH];
        const float* xp = xphy + (size_t)g * 3;     // step 0
#pragma unroll
        for (int i = 0; i < CH; i++) {
            rP[i] = xp[0]; rT[i] = xp[1]; rE[i] = xp[2];
            xp += (size_t)G_CELLS * 3;
        }
        for (int k = 0; k < NCHUNK - 1; ++k) {       // chunks 0..71
            if (((k & 1) == 0) && k >= 4) {
                BAR_SYNC(3 + ((k >> 1) & 1));        // consumer freed super (k/2-2)
                flush_q(k - 4);
                flush_q(k - 3);
            }
            const int s = k & 3;
#pragma unroll
            for (int i = 0; i < CH; i++) {
                const float P = rP[i], Tm = rT[i], PE = rE[i];
                rP[i] = xp[0]; rT[i] = xp[1]; rE[i] = xp[2];
                xp += (size_t)G_CELLS * 3;
                const float inflow = snow_adv(P, Tm);
                buf[s][i][lane] = make_float2(inflow, PE);
            }
            if (k & 1) BAR_ARRIVE(1 + ((k >> 1) & 1));   // super-chunk full
        }
        {   // final chunk 72 (slot 0): no loads
            BAR_SYNC(3);                              // consumer freed super 34
            flush_q(68);
            flush_q(69);
#pragma unroll
            for (int i = 0; i < CH; i++) {
                const float inflow = snow_adv(rP[i], rT[i]);
                buf[0][i][lane] = make_float2(inflow, rE[i]);
            }
            BAR_ARRIVE(1);                            // "super 36" full
        }
        // Tail flushes as consumer finishes.
        BAR_SYNC(4);   // super 35 freed
        flush_q(70);
        flush_q(71);
        BAR_SYNC(3);   // super 36 (chunk 72) freed
        flush_q(72);
    } else {
        // -------- CONSUMER: SM/SUZ/SLZ chain, Q to smem --------
        const float BETA = phy[0], FC = phy[1], K0 = phy[2], K1 = phy[3];
        const float K2 = phy[4], LP = phy[5], PERCmax = phy[6], UZL = phy[7];
        const float BETAET = phy[12], C = phy[13];

        const float invFC = 1.0f / FC;
        const float clgA  = BETA   * lg2f_(invFC);
        const float clgB  = BETAET * lg2f_(1.0f / (LP * FC));
        const float oneK0 = 1.0f - K0;
        const float K0UZL = K0 * UZL;
        const float oneK1 = 1.0f - K1;

        float SM = 0.001f, SUZ = 0.001f, SLZ = 0.001f;
        float CSLZ = C * SLZ;
        float omcf = 1.0f - CSLZ * invFC;

        for (int k = 0; k < NCHUNK; ++k) {
            if ((k & 1) == 0) BAR_SYNC(1 + ((k >> 1) & 1));  // super full
            const int s = k & 3;
            float2 v[CH];
#pragma unroll
            for (int i = 0; i < CH; i++) v[i] = buf[s][i][lane];

#pragma unroll
            for (int i = 0; i < CH; i++) {
                const float inflow = v[i].x, PETt = v[i].y;

                const float t1 = SM + inflow;
                // e1 = min((SM/FC)^BETA, 1), clamp in log domain
                const float s1 = fminf(fmaf(BETA, lg2f_(SM), clgA), 0.0f);
                const float e1 = ex2f_(s1);
                const float SM1 = fmaf(-inflow, e1, t1);   // >= SM
                const float SM2 = fminf(SM1, FC);          // parallel to lg2
                // e2 UNCLAMPED; floor3 absorbs both ef<=1 and SM1<=FC caps
                const float e2 = ex2f_(fmaf(BETAET, lg2f_(SM1), clgB));
                const float floor3 = fmaxf(SM2 - PETt, NEARZERO_F);  // off-path

                // ---- off-path response front half (fills e2 MUFU latency) ----
                const float SUZ1 = SUZ + (t1 - SM2);       // + recharge+excess
                const float PERC = fminf(SUZ1, PERCmax);
                const float SUZ2 = fmaxf(SUZ1 - PERCmax, 0.0f);
                const float SUZ3 = fminf(SUZ2, fmaf(oneK0, SUZ2, K0UZL));
                SUZ = oneK1 * SUZ3;
                const float Q01 = SUZ2 - SUZ;

                // ---- chain tail ----
                const float SM3 = fmaxf(fmaf(-PETt, e2, SM2), floor3);
                // capillary: cap = CSLZ*(1-SM3/FC); clamps proven redundant
                // (C<1 => CSLZ<SLZ; SM3<=FC => factor in [0,1])
                const float SMn = fmaf(omcf, SM3, CSLZ);
                const float cap = SMn - SM3;               // off-path
                SM = SMn;

                // ---- off-path response back half ----
                const float SLZ1 = fmaxf(SLZ - cap, NEARZERO_F) + PERC;
                const float Q2 = K2 * SLZ1;
                SLZ = SLZ1 - Q2;
                CSLZ = C * SLZ;
                omcf = fmaf(-CSLZ, invFC, 1.0f);

                qbuf[s][i][lane] = Q01 + Q2;   // STS instead of STG
            }
            if ((k & 1) || k == NCHUNK - 1)
                BAR_ARRIVE(3 + ((k >> 1) & 1));   // super free + Q ready
        }
    }
}

extern "C" void kernel_launch(void* const* d_in, const int* in_sizes, int n_in,
                              void* d_out, int out_size) {
    const float* xphy   = (const float*)d_in[0];   // 730*8000*3
    const float* params = (const float*)d_in[1];   // 730*8000*14
    float* out = (float*)d_out;                    // 730*8000

    hbv_kernel<<<125, 128>>>(xphy, params, out);   // 125 * 64 cells = 8000
}

// round 12
// speedup vs baseline: 1.3131x; 1.1465x over previous
#include <cuda_runtime.h>
#include <cstddef>

#define G_CELLS 8000
#define T_STEPS 730
#define CH 10              // steps per chunk; 730 = 10 * 73
#define NCHUNK 73
#define CPB 64             // cells per block; 8000 = 125 * 64
#define NEARZERO_F 1e-5f

__device__ __forceinline__ float ex2f_(float x) {
    float r; asm("ex2.approx.f32 %0, %1;" : "=f"(r) : "f"(x)); return r;
}
__device__ __forceinline__ float lg2f_(float x) {
    float r; asm("lg2.approx.f32 %0, %1;" : "=f"(r) : "f"(x)); return r;
}

// Named barriers at SUPER-CHUNK (2-chunk) granularity, 4-slot data ring.
// full: id 1+(j&1) (producer -> consumer), free: id 3+(j&1) (consumer -> producer),
// j = super-chunk index. count = 128. bar.sync/arrive carry membar.cta-equivalent
// fence semantics.
#define BAR_SYNC(id)   asm volatile("bar.sync %0, 128;"   :: "r"(id) : "memory")
#define BAR_ARRIVE(id) asm volatile("bar.arrive %0, 128;" :: "r"(id) : "memory")

__global__ __launch_bounds__(128, 1) void hbv_kernel(
    const float* __restrict__ xphy,    // [730, 8000, 3] (P, T, PET)
    const float* __restrict__ params,  // [730, 8000, 14]
    float* __restrict__ out)           // [730, 8000]
{
    __shared__ float2 buf[4][CH][CPB];   // (inflow, PET) producer -> consumer
    __shared__ float  qbuf[4][CH][CPB];  // Q results    consumer -> producer

    const int tid  = threadIdx.x;
    const int lane = tid & 63;                 // cell slot within block
    const bool is_producer = (tid >= 64);
    const int g = blockIdx.x * CPB + lane;     // always < 8000

    // BETA, FC, K0, K1, K2, LP, PERCmax, UZL, TT, CFMAX, CFR, CWH, BETAET, C
    const float lo[14] = {1.0f, 50.0f, 0.05f, 0.01f, 0.001f, 0.2f, 0.0f,
                          0.0f, -2.5f, 0.5f, 0.0f, 0.0f, 0.3f, 0.0f};
    const float hi[14] = {6.0f, 1000.0f, 0.9f, 0.5f, 0.2f, 1.0f, 10.0f,
                          100.0f, 2.5f, 10.0f, 0.1f, 0.2f, 5.0f, 1.0f};

    const float* pr = params + ((size_t)(T_STEPS - 1) * G_CELLS + (size_t)g) * 14;
    float phy[14];
#pragma unroll
    for (int i = 0; i < 14; i++) {
        const float s = 1.0f / (1.0f + __expf(-pr[i]));
        phy[i] = fmaf(s, hi[i] - lo[i], lo[i]);
    }

    if (is_producer) {
        // -------- PRODUCER: snow recurrence + input loads + Q store-out --------
        const float TT = phy[8], CFMAX = phy[9], CWH = phy[11];
        const float CFRCF = phy[10] * phy[9];

        float SP = 0.001f, MW = 0.001f;

        auto snow_adv = [&](float P, float Tm) -> float {
            const bool  rain = (Tm >= TT);
            const float RAIN = rain ? P : 0.0f;
            const float SNOW = rain ? 0.0f : P;
            const float w    = (rain ? CFMAX : CFRCF) * (Tm - TT);
            const float SP1  = SP + SNOW;
            const float transfer = fminf(fmaxf(w, -MW), SP1);
            SP = SP1 - transfer;
            const float MW2 = MW + transfer;
            const float v   = fmaf(-CWH, SP, MW2);
            const float tosoil = fmaxf(v, 0.0f);
            MW = MW2 - tosoil;
            return RAIN + tosoil;
        };

        auto flush_q = [&](int m) {
            float* o = out + (size_t)(m * CH) * G_CELLS + g;
            const int s = m & 3;
#pragma unroll
            for (int i = 0; i < CH; i++) {
                o[(size_t)i * G_CELLS] = qbuf[s][i][lane];
            }
        };

        // Raw-input ring: next chunk's inputs, loaded one chunk early.
        float rP[CH], rT[CH], rE[CH];
        const float* xp = xphy + (size_t)g * 3;     // step 0
#pragma unroll
        for (int i = 0; i < CH; i++) {
            rP[i] = xp[0]; rT[i] = xp[1]; rE[i] = xp[2];
            xp += (size_t)G_CELLS * 3;
        }
        for (int k = 0; k < NCHUNK - 1; ++k) {       // chunks 0..71
            if (((k & 1) == 0) && k >= 4) {
                BAR_SYNC(3 + ((k >> 1) & 1));        // consumer freed super (k/2-2)
                flush_q(k - 4);
                flush_q(k - 3);
            }
            const int s = k & 3;
#pragma unroll
            for (int i = 0; i < CH; i++) {
                const float P = rP[i], Tm = rT[i], PE = rE[i];
                rP[i] = xp[0]; rT[i] = xp[1]; rE[i] = xp[2];
                xp += (size_t)G_CELLS * 3;
                const float inflow = snow_adv(P, Tm);
                buf[s][i][lane] = make_float2(inflow, PE);
            }
            if (k & 1) BAR_ARRIVE(1 + ((k >> 1) & 1));   // super-chunk full
        }
        {   // final chunk 72 (slot 0): no loads
            BAR_SYNC(3);                              // consumer freed super 34
            flush_q(68);
            flush_q(69);
#pragma unroll
            for (int i = 0; i < CH; i++) {
                const float inflow = snow_adv(rP[i], rT[i]);
                buf[0][i][lane] = make_float2(inflow, rE[i]);
            }
            BAR_ARRIVE(1);                            // "super 36" full
        }
        // Tail flushes as consumer finishes.
        BAR_SYNC(4);   // super 35 freed
        flush_q(70);
        flush_q(71);
        BAR_SYNC(3);   // super 36 (chunk 72) freed
        flush_q(72);
    } else {
        // -------- CONSUMER: SM/SUZ/SLZ chain (rotated: lgSM carried) --------
        const float BETA = phy[0], FC = phy[1], K0 = phy[2], K1 = phy[3];
        const float K2 = phy[4], LP = phy[5], PERCmax = phy[6], UZL = phy[7];
        const float BETAET = phy[12], C = phy[13];

        const float invFC = 1.0f / FC;
        const float clgA  = BETA   * lg2f_(invFC);
        const float clgB  = BETAET * lg2f_(1.0f / (LP * FC));
        const float oneK0 = 1.0f - K0;
        const float K0UZL = K0 * UZL;
        const float oneK1 = 1.0f - K1;

        float SM = 0.001f, SUZ = 0.001f, SLZ = 0.001f;
        float CSLZ = C * SLZ;
        float omcf = 1.0f - CSLZ * invFC;
        float lgSM = lg2f_(SM);                 // rotated loop-carried value

        // One step: the first MUFU (lg2 of the *next* SM) is issued at the end
        // of this step, with the off-path tail textually inside its shadow.
        auto do_chunk = [&](int k) {
            const int s = k & 3;
            float2 v[CH];
#pragma unroll
            for (int i = 0; i < CH; i++) v[i] = buf[s][i][lane];

#pragma unroll
            for (int i = 0; i < CH; i++) {
                const float inflow = v[i].x, PETt = v[i].y;

                // --- chain head (lgSM already computed last step) ---
                const float s1 = fminf(fmaf(BETA, lgSM, clgA), 0.0f);
                const float e1 = ex2f_(s1);
                // off-path in e1 shadow:
                const float t1 = SM + inflow;

                const float SM1 = fmaf(-inflow, e1, t1);   // >= SM
                const float lg1 = lg2f_(SM1);
                // off-path in lg1 shadow:
                const float SM2 = fminf(SM1, FC);
                const float floor3 = fmaxf(SM2 - PETt, NEARZERO_F);
                const float d = t1 - SM2;                  // recharge + excess

                const float e2 = ex2f_(fmaf(BETAET, lg1, clgB));
                // off-path in e2 shadow (SUZ front half):
                const float SUZ1 = SUZ + d;
                const float PERC = fminf(SUZ1, PERCmax);
                const float SUZ2 = fmaxf(SUZ1 - PERCmax, 0.0f);
                const float SUZ3 = fminf(SUZ2, fmaf(oneK0, SUZ2, K0UZL));
                SUZ = oneK1 * SUZ3;
                const float Q01 = SUZ2 - SUZ;

                // --- chain tail ---
                const float SM3 = fmaxf(fmaf(-PETt, e2, SM2), floor3);
                const float SMn = fmaf(omcf, SM3, CSLZ);   // + capillary
                SM = SMn;
                lgSM = lg2f_(SMn);             // ROTATED: next step's lg2 now
                // off-path tail in lgSM shadow:
                const float cap = SMn - SM3;
                const float SLZ1 = fmaxf(SLZ - cap, NEARZERO_F) + PERC;
                const float Q2 = K2 * SLZ1;
                SLZ = SLZ1 - Q2;
                CSLZ = C * SLZ;
                omcf = fmaf(-CSLZ, invFC, 1.0f);
                qbuf[s][i][lane] = Q01 + Q2;
            }
        };

        // 36 full super-chunks (chunks 0..71), then final chunk 72.
        for (int j = 0; j < 36; ++j) {
            BAR_SYNC(1 + (j & 1));              // super full (acquire)
            do_chunk(2 * j);
            do_chunk(2 * j + 1);
            BAR_ARRIVE(3 + (j & 1));            // super free + Q ready (release)
        }
        BAR_SYNC(1);                            // "super 36" full
        do_chunk(72);
        BAR_ARRIVE(3);
    }
}

extern "C" void kernel_launch(void* const* d_in, const int* in_sizes, int n_in,
                              void* d_out, int out_size) {
    const float* xphy   = (const float*)d_in[0];   // 730*8000*3
    const float* params = (const float*)d_in[1];   // 730*8000*14
    float* out = (float*)d_out;                    // 730*8000

    hbv_kernel<<<125, 128>>>(xphy, params, out);   // 125 * 64 cells = 8000
}